// round 2
// baseline (speedup 1.0000x reference)
#include <cuda_runtime.h>

#define VOCAB 32000
#define HID   768
#define HS1   128
#define MT    128
#define KT    32
#define NT    128

// dtype flag for tk: 1 = int64 storage, 0 = int32 storage
__device__ int g_tk_is64;

// One-warp probe: if tk is int64, every odd 32-bit word is the (zero) high half.
// If int32, odd words are actual tokens; 31 of them all being zero ~ impossible.
__global__ void probe_tk_kernel(const unsigned int* __restrict__ w) {
    int lane = threadIdx.x;
    unsigned int v = 0u;
    if (lane >= 1) v = w[2 * lane - 1];   // words 1,3,...,61
    unsigned int any = __ballot_sync(0xffffffffu, v != 0u);
    if (lane == 0) g_tk_is64 = (any == 0u) ? 1 : 0;
}

__global__ __launch_bounds__(256, 2)
void classifier_kernel(const int*   __restrict__ tkw,   // tk as 32-bit words
                      const float* __restrict__ hs0,   // [M, 768]
                      const float* __restrict__ W1,    // [32768, 128]
                      const float* __restrict__ b1,    // [128]
                      const float* __restrict__ W2,    // [128]
                      const float* __restrict__ b2,    // [1]
                      float*       __restrict__ out)   // [M]
{
    __shared__ float As[MT][KT + 4];   // hs0 tile, padded rows (16B-aligned stride)
    __shared__ float Bs[KT][NT];       // W1 hidden-part tile
    __shared__ float red[MT][17];      // per-row partial sums (pad avoids conflicts)

    const int tid = threadIdx.x;
    const int tx  = tid & 15;          // 16 col-groups
    const int ty  = tid >> 4;          // 16 row-groups
    const int m0  = blockIdx.x * MT;
    const float* __restrict__ Wh = W1 + (size_t)VOCAB * HS1;

    float acc[8][8];
#pragma unroll
    for (int i = 0; i < 8; i++)
#pragma unroll
        for (int j = 0; j < 8; j++) acc[i][j] = 0.f;

    const int fa = tid & 7;            // float4 index within a 32-float A row
    const int ra = tid >> 3;           // 0..31
    const int fb = tid & 31;           // float4 index within a 128-float B row
    const int rb = tid >> 5;           // 0..7

    for (int k0 = 0; k0 < HID; k0 += KT) {
        // Load A tile: 128 rows x 32 K  (coalesced float4, conflict-free STS.128)
#pragma unroll
        for (int it = 0; it < 4; it++) {
            int r = ra + it * 32;
            float4 v = *(const float4*)&hs0[(size_t)(m0 + r) * HID + k0 + fa * 4];
            *(float4*)&As[r][fa * 4] = v;
        }
        // Load B tile: 32 K x 128 N (coalesced float4)
#pragma unroll
        for (int it = 0; it < 4; it++) {
            int k = rb + it * 8;
            float4 v = *(const float4*)&Wh[(size_t)(k0 + k) * HS1 + fb * 4];
            *(float4*)&Bs[k][fb * 4] = v;
        }
        __syncthreads();

#pragma unroll
        for (int k = 0; k < KT; k++) {
            float a[8];
#pragma unroll
            for (int i = 0; i < 8; i++) a[i] = As[ty * 8 + i][k];   // broadcast LDS
            // split-N column groups: cols tx*4..tx*4+3 and 64+tx*4.. (phase-conflict-free)
            float4 bb0 = *(const float4*)&Bs[k][tx * 4];
            float4 bb1 = *(const float4*)&Bs[k][64 + tx * 4];
            float bj[8] = {bb0.x, bb0.y, bb0.z, bb0.w, bb1.x, bb1.y, bb1.z, bb1.w};
#pragma unroll
            for (int i = 0; i < 8; i++)
#pragma unroll
                for (int j = 0; j < 8; j++)
                    acc[i][j] = fmaf(a[i], bj[j], acc[i][j]);
        }
        __syncthreads();
    }

    // ---- fused epilogue: gather + bias + relu + dot(W2) + b2 ----
    const int is64 = g_tk_is64;
    float4 ba = *(const float4*)&b1[tx * 4];
    float4 bb = *(const float4*)&b1[64 + tx * 4];
    float4 wa = *(const float4*)&W2[tx * 4];
    float4 wb = *(const float4*)&W2[64 + tx * 4];
    float b1j[8] = {ba.x, ba.y, ba.z, ba.w, bb.x, bb.y, bb.z, bb.w};
    float w2j[8] = {wa.x, wa.y, wa.z, wa.w, wb.x, wb.y, wb.z, wb.w};

    float partial[8];
#pragma unroll
    for (int i = 0; i < 8; i++) {
        int m   = m0 + ty * 8 + i;
        int tok = tkw[is64 ? 2 * m : m];          // low word == value for int64 too
        const float* __restrict__ g = W1 + (size_t)tok * HS1;
        float4 g0 = *(const float4*)&g[tx * 4];
        float4 g1 = *(const float4*)&g[64 + tx * 4];
        float gj[8] = {g0.x, g0.y, g0.z, g0.w, g1.x, g1.y, g1.z, g1.w};
        float s = 0.f;
#pragma unroll
        for (int j = 0; j < 8; j++) {
            float h = acc[i][j] + gj[j] + b1j[j];
            h = fmaxf(h, 0.f);
            s = fmaf(h, w2j[j], s);
        }
        partial[i] = s;
    }
#pragma unroll
    for (int i = 0; i < 8; i++) red[ty * 8 + i][tx] = partial[i];
    __syncthreads();

    if (tid < MT) {
        float s = 0.f;
#pragma unroll
        for (int x = 0; x < 16; x++) s += red[tid][x];
        out[m0 + tid] = s + b2[0];
    }
}

extern "C" void kernel_launch(void* const* d_in, const int* in_sizes, int n_in,
                              void* d_out, int out_size)
{
    const int*   tkw = (const int*)d_in[0];
    const float* hs0 = (const float*)d_in[1];
    const float* W1  = (const float*)d_in[2];
    const float* b1  = (const float*)d_in[3];
    const float* W2  = (const float*)d_in[4];
    const float* b2  = (const float*)d_in[5];
    float* out = (float*)d_out;

    const int M = in_sizes[1] / HID;   // tokens, derived from hs0 (dtype-agnostic)

    probe_tk_kernel<<<1, 32>>>((const unsigned int*)tkw);
    classifier_kernel<<<M / MT, 256>>>(tkw, hs0, W1, b1, W2, b2, out);
}

// round 7
// speedup vs baseline: 3.6113x; 3.6113x over previous
#include <cuda_runtime.h>
#include <cuda_bf16.h>
#include <cstdint>

#define VOCAB 32000
#define HID   768
#define HS1   128
#define MT    128
#define KT    32
#define NKT   (HID / KT)          // 24 K-tiles

#define SA_BYTES 160              // A row stride: 40 f32 (2-phase LDS.64, optimal)
#define SB_BYTES 80               // B row stride: 40 bf16 (1-phase LDS.32)
#define OFF_B0   20480            // 128*160
#define OFF_B1   30720            // + 128*80
#define STAGE_BYTES 40960
#define SMEM_BYTES  81920         // 2 stages
#define SG       132              // epilogue gather row stride (f32)
#define OFF_RED  68608            // after G (128*132*4 = 67584)

__device__ int g_tk_is64;
__device__ __nv_bfloat16 g_Bbig[HS1 * HID];    // W1 hidden part [n][k], bf16 big
__device__ __nv_bfloat16 g_Bsmall[HS1 * HID];  // residual

__device__ __forceinline__ uint32_t smem_u32(const void* p) {
    uint32_t a;
    asm("{ .reg .u64 t; cvta.to.shared.u64 t, %1; cvt.u32.u64 %0, t; }" : "=r"(a) : "l"(p));
    return a;
}
__device__ __forceinline__ void cp16(uint32_t dst, const void* src) {
    asm volatile("cp.async.ca.shared.global [%0], [%1], 16;" :: "r"(dst), "l"(src));
}
__device__ __forceinline__ void cp8(uint32_t dst, const void* src) {
    asm volatile("cp.async.ca.shared.global [%0], [%1], 8;" :: "r"(dst), "l"(src));
}
#define CP_COMMIT() asm volatile("cp.async.commit_group;" ::: "memory")
#define CP_WAIT1()  asm volatile("cp.async.wait_group 1;" ::: "memory")

#define MMA_BF16(d, a, b0, b1)                                                  \
    asm volatile("mma.sync.aligned.m16n8k16.row.col.f32.bf16.bf16.f32 "         \
        "{%0,%1,%2,%3}, {%4,%5,%6,%7}, {%8,%9}, {%0,%1,%2,%3};"                 \
        : "+f"((d)[0]), "+f"((d)[1]), "+f"((d)[2]), "+f"((d)[3])                \
        : "r"((a)[0]), "r"((a)[1]), "r"((a)[2]), "r"((a)[3]), "r"(b0), "r"(b1))

// ---------------- small kernels ----------------
__global__ void probe_tk_kernel(const unsigned int* __restrict__ w) {
    int lane = threadIdx.x;
    unsigned int v = 0u;
    if (lane >= 1) v = w[2 * lane - 1];
    unsigned int any = __ballot_sync(0xffffffffu, v != 0u);
    if (lane == 0) g_tk_is64 = (any == 0u) ? 1 : 0;
}

// transpose + bf16-split W1 hidden part: Bb[n][k] = bf16(Wh[k][n]), Bs = residual
__global__ void prep_w_kernel(const float* __restrict__ W1) {
    int idx = blockIdx.x * blockDim.x + threadIdx.x;   // 0 .. 128*768-1
    int n = idx / HID, k = idx % HID;
    float v = W1[(size_t)(VOCAB + k) * HS1 + n];
    __nv_bfloat16 b = __float2bfloat16_rn(v);
    g_Bbig[idx] = b;
    g_Bsmall[idx] = __float2bfloat16_rn(v - __bfloat162float(b));
}

// ---------------- main fused kernel ----------------
__global__ __launch_bounds__(256, 2)
void cls_mma_kernel(const int*   __restrict__ tkw,
                    const float* __restrict__ hs0,
                    const float* __restrict__ W1,
                    const float* __restrict__ b1,
                    const float* __restrict__ W2,
                    const float* __restrict__ b2,
                    float*       __restrict__ out)
{
    extern __shared__ char smem[];
    const uint32_t sb = smem_u32(smem);
    const int tid = threadIdx.x;
    const int lane = tid & 31, wid = tid >> 5;
    const int wm = wid & 3;            // warp row (4)  -> 32 M-rows each
    const int wn = wid >> 2;           // warp col (2)  -> 64 N-cols each
    const int g  = lane >> 2;          // 0..7  (fragment row group)
    const int q4 = lane & 3;           // 0..3  (fragment col group)
    const int m0 = blockIdx.x * MT;

    float acc[2][8][4];
#pragma unroll
    for (int mt = 0; mt < 2; mt++)
#pragma unroll
        for (int j = 0; j < 8; j++)
#pragma unroll
            for (int e = 0; e < 4; e++) acc[mt][j][e] = 0.f;

    // ---- stage loader: A f32 tile + B bf16 (big,small) tiles via cp.async ----
    auto load_stage = [&](int s, int k0) {
        uint32_t base = sb + s * STAGE_BYTES;
#pragma unroll
        for (int i = 0; i < 4; i++) {                    // A: 1024 x 16B
            int q = i * 256 + tid, r = q >> 3, c = q & 7;
            cp16(base + r * SA_BYTES + c * 16,
                 hs0 + (size_t)(m0 + r) * HID + k0 + c * 4);
        }
#pragma unroll
        for (int i = 0; i < 4; i++) {                    // B: 2 x 1024 x 8B
            int q = i * 256 + tid, n = q >> 3, c = q & 7;
            cp8(base + OFF_B0 + n * SB_BYTES + c * 8, g_Bbig   + (size_t)n * HID + k0 + c * 4);
            cp8(base + OFF_B1 + n * SB_BYTES + c * 8, g_Bsmall + (size_t)n * HID + k0 + c * 4);
        }
        CP_COMMIT();
    };

    // ---- compute one K-tile from stage s ----
    auto compute = [&](int s) {
        uint32_t a_base  = sb + s * STAGE_BYTES;
        uint32_t bb_base = a_base + OFF_B0;
        uint32_t bs_base = a_base + OFF_B1;
#pragma unroll
        for (int ks = 0; ks < 2; ks++) {
            const int kk = ks * 16 + 2 * q4;             // first k of this thread's pair
            uint32_t ab[2][4], as[2][4];
#pragma unroll
            for (int mt = 0; mt < 2; mt++) {
                int r0 = wm * 32 + mt * 16 + g;
#pragma unroll
                for (int p = 0; p < 4; p++) {            // a0..a3 frag order
                    int rr = r0 + (p & 1) * 8;
                    int kc = kk + (p >> 1) * 8;
                    float vx, vy;
                    asm volatile("ld.shared.v2.f32 {%0,%1}, [%2];"
                                 : "=f"(vx), "=f"(vy)
                                 : "r"(a_base + rr * SA_BYTES + kc * 4));
                    __nv_bfloat162 hb = __floats2bfloat162_rn(vx, vy);
                    float rx = vx - __low2float(hb);
                    float ry = vy - __high2float(hb);
                    __nv_bfloat162 hs = __floats2bfloat162_rn(rx, ry);
                    ab[mt][p] = *(uint32_t*)&hb;
                    as[mt][p] = *(uint32_t*)&hs;
                }
            }
#pragma unroll
            for (int j = 0; j < 8; j++) {
                int n = wn * 64 + j * 8 + g;
                uint32_t boff = n * SB_BYTES + kk * 2;
                uint32_t b0b, b1b, b0s, b1s;
                asm volatile("ld.shared.b32 %0, [%1];" : "=r"(b0b) : "r"(bb_base + boff));
                asm volatile("ld.shared.b32 %0, [%1];" : "=r"(b1b) : "r"(bb_base + boff + 16));
                asm volatile("ld.shared.b32 %0, [%1];" : "=r"(b0s) : "r"(bs_base + boff));
                asm volatile("ld.shared.b32 %0, [%1];" : "=r"(b1s) : "r"(bs_base + boff + 16));
#pragma unroll
                for (int mt = 0; mt < 2; mt++) {
                    MMA_BF16(acc[mt][j], ab[mt], b0b, b1b);   // Ab*Bb
                    MMA_BF16(acc[mt][j], ab[mt], b0s, b1s);   // Ab*Bs
                    MMA_BF16(acc[mt][j], as[mt], b0b, b1b);   // As*Bb
                }
            }
        }
    };

    // ---- pipelined mainloop (2-stage) ----
    load_stage(0, 0);
    load_stage(1, KT);
    for (int t = 0; t < NKT; t++) {
        CP_WAIT1();
        __syncthreads();
        compute(t & 1);
        __syncthreads();
        if (t + 2 < NKT) load_stage(t & 1, (t + 2) * KT);
        else             CP_COMMIT();                    // empty group keeps wait math valid
    }

    // ---- epilogue: gather + bias + relu + dot(W2) + reduce ----
    const int is64 = g_tk_is64;
    {   // stage gather matrix G[128][128] f32 into (reused) SMEM
        int row = tid >> 1, half = tid & 1;
        int m = m0 + row;
        int tok = tkw[is64 ? 2 * m : m];
        const float4* src = (const float4*)(W1 + (size_t)tok * HS1) + half * 16;
        float4* dst = (float4*)((float*)smem + row * SG + half * 64);
#pragma unroll
        for (int i = 0; i < 16; i++) dst[i] = src[i];
    }
    float b1v[16], w2v[16];
#pragma unroll
    for (int j = 0; j < 8; j++) {
        int col = wn * 64 + j * 8 + 2 * q4;
        b1v[j * 2]     = b1[col];     b1v[j * 2 + 1] = b1[col + 1];
        w2v[j * 2]     = W2[col];     w2v[j * 2 + 1] = W2[col + 1];
    }
    __syncthreads();

    float* red = (float*)(smem + OFF_RED);
    const float* G = (const float*)smem;
#pragma unroll
    for (int mt = 0; mt < 2; mt++)
#pragma unroll
        for (int h = 0; h < 2; h++) {
            int row = wm * 32 + mt * 16 + h * 8 + g;
            const float* Gr = G + row * SG + wn * 64;
            float p = 0.f;
#pragma unroll
            for (int j = 0; j < 8; j++) {
                float x0 = acc[mt][j][h * 2 + 0] + Gr[j * 8 + 2 * q4]     + b1v[j * 2];
                float x1 = acc[mt][j][h * 2 + 1] + Gr[j * 8 + 2 * q4 + 1] + b1v[j * 2 + 1];
                p = fmaf(fmaxf(x0, 0.f), w2v[j * 2],     p);
                p = fmaf(fmaxf(x1, 0.f), w2v[j * 2 + 1], p);
            }
            red[row * 9 + wn * 4 + q4] = p;
        }
    __syncthreads();

    if (tid < MT) {
        float s = 0.f;
#pragma unroll
        for (int x = 0; x < 8; x++) s += red[tid * 9 + x];
        out[m0 + tid] = s + b2[0];
    }
}

extern "C" void kernel_launch(void* const* d_in, const int* in_sizes, int n_in,
                              void* d_out, int out_size)
{
    const int*   tkw = (const int*)d_in[0];
    const float* hs0 = (const float*)d_in[1];
    const float* W1  = (const float*)d_in[2];
    const float* b1  = (const float*)d_in[3];
    const float* W2  = (const float*)d_in[4];
    const float* b2  = (const float*)d_in[5];
    float* out = (float*)d_out;

    const int M = in_sizes[1] / HID;   // tokens from hs0 (tk-dtype agnostic)

    cudaFuncSetAttribute(cls_mma_kernel,
                         cudaFuncAttributeMaxDynamicSharedMemorySize, SMEM_BYTES);

    probe_tk_kernel<<<1, 32>>>((const unsigned int*)tkw);
    prep_w_kernel<<<(HS1 * HID) / 256, 256>>>(W1);
    cls_mma_kernel<<<M / MT, 256, SMEM_BYTES>>>(tkw, hs0, W1, b1, W2, b2, out);
}

// round 8
// speedup vs baseline: 4.8477x; 1.3424x over previous
#include <cuda_runtime.h>
#include <cuda_fp16.h>
#include <cstdint>

#define VOCAB 32000
#define HID   768
#define HS1   128
#define MT    128
#define KT    32
#define NKT   (HID / KT)          // 24 K-tiles

#define SA_BYTES 160              // A row stride (40 f32): 2-phase LDS.64
#define SB_BYTES 160              // B packed row stride (128B data + 32B pad)
#define OFF_B    20480            // 128*160
#define STAGE_BYTES 40960
#define SMEM_BYTES  81920         // 2 stages
#define SG       132              // epilogue gather row stride (f32)
#define OFF_RED  68608            // after G (128*132*4 = 67584)

__device__ int g_tk_is64;
// packed fp16 weights: per (tile t, n): 128B = [ks][chunk][q4-pair]{h2,r2}
__device__ uint4 g_Bpk[(size_t)NKT * HS1 * 8];

__device__ __forceinline__ uint32_t smem_u32(const void* p) {
    uint32_t a;
    asm("{ .reg .u64 t; cvta.to.shared.u64 t, %1; cvt.u32.u64 %0, t; }" : "=r"(a) : "l"(p));
    return a;
}
__device__ __forceinline__ void cp16(uint32_t dst, const void* src) {
    asm volatile("cp.async.ca.shared.global [%0], [%1], 16;" :: "r"(dst), "l"(src));
}
#define CP_COMMIT() asm volatile("cp.async.commit_group;" ::: "memory")
#define CP_WAIT1()  asm volatile("cp.async.wait_group 1;" ::: "memory")

#define MMA_F16(d, a, b0, b1)                                                   \
    asm volatile("mma.sync.aligned.m16n8k16.row.col.f32.f16.f16.f32 "           \
        "{%0,%1,%2,%3}, {%4,%5,%6,%7}, {%8,%9}, {%0,%1,%2,%3};"                 \
        : "+f"((d)[0]), "+f"((d)[1]), "+f"((d)[2]), "+f"((d)[3])                \
        : "r"((a)[0]), "r"((a)[1]), "r"((a)[2]), "r"((a)[3]), "r"(b0), "r"(b1))

// ---- prep: coalesced transpose + fp16 (value, residual) split; probe folded in ----
__global__ void prep_w_kernel(const float* __restrict__ W1,
                              const unsigned int* __restrict__ tkw) {
    __shared__ float sm[KT][HS1 + 4];
    const int t = blockIdx.x, tid = threadIdx.x;
    if (t == 0 && tid < 32) {   // tk dtype probe: int64 -> all odd words zero
        unsigned int v = (tid >= 1) ? tkw[2 * tid - 1] : 0u;
        unsigned int any = __ballot_sync(0xffffffffu, v != 0u);
        if (tid == 0) g_tk_is64 = (any == 0u) ? 1 : 0;
    }
#pragma unroll
    for (int i = 0; i < 16; i++) {            // coalesced read 32k x 128n
        int u = i * 256 + tid;
        int k = u >> 7, n = u & 127;
        sm[k][n] = W1[(size_t)(VOCAB + t * KT + k) * HS1 + n];
    }
    __syncthreads();
#pragma unroll
    for (int i = 0; i < 4; i++) {             // emit packed fragment layout
        int u = i * 256 + tid;
        int n = u >> 3, c = u & 7;
        int ks = c >> 2, chunk = (c >> 1) & 1, q4a = 2 * (c & 1);
        uint4 o;
#pragma unroll
        for (int q = 0; q < 2; q++) {
            int k0 = ks * 16 + 2 * (q4a + q) + chunk * 8;   // 0..30
            float x0 = sm[k0][n], x1 = sm[k0 + 1][n];
            __half2 h = __floats2half2_rn(x0, x1);
            __half2 r = __floats2half2_rn(x0 - __low2float(h), x1 - __high2float(h));
            ((uint32_t*)&o)[q * 2]     = *(uint32_t*)&h;
            ((uint32_t*)&o)[q * 2 + 1] = *(uint32_t*)&r;
        }
        g_Bpk[((size_t)t * HS1 + n) * 8 + c] = o;
    }
}

// ---------------- main fused kernel ----------------
__global__ __launch_bounds__(256, 2)
void cls_mma_kernel(const int*   __restrict__ tkw,
                    const float* __restrict__ hs0,
                    const float* __restrict__ W1,
                    const float* __restrict__ b1,
                    const float* __restrict__ W2,
                    const float* __restrict__ b2,
                    float*       __restrict__ out)
{
    extern __shared__ char smem[];
    const uint32_t sb = smem_u32(smem);
    const int tid = threadIdx.x;
    const int lane = tid & 31, wid = tid >> 5;
    const int wm = wid & 3;            // warp row (4) -> 32 M-rows
    const int wn = wid >> 2;           // warp col (2) -> 64 N-cols
    const int g  = lane >> 2;          // 0..7
    const int q4 = lane & 3;           // 0..3
    const int m0 = blockIdx.x * MT;

    float acc[2][8][4];
#pragma unroll
    for (int mt = 0; mt < 2; mt++)
#pragma unroll
        for (int j = 0; j < 8; j++)
#pragma unroll
            for (int e = 0; e < 4; e++) acc[mt][j][e] = 0.f;

    auto load_stage = [&](int s, int t) {
        uint32_t base = sb + s * STAGE_BYTES;
        const int k0 = t * KT;
#pragma unroll
        for (int i = 0; i < 4; i++) {                    // A: f32 128r x 32k
            int q = i * 256 + tid, r = q >> 3, c = q & 7;
            cp16(base + r * SA_BYTES + c * 16,
                 hs0 + (size_t)(m0 + r) * HID + k0 + c * 4);
        }
        const uint4* src = g_Bpk + (size_t)t * HS1 * 8;  // B packed: 128n x 128B
#pragma unroll
        for (int i = 0; i < 4; i++) {
            int q = i * 256 + tid, n = q >> 3, c = q & 7;
            cp16(base + OFF_B + n * SB_BYTES + c * 16, src + n * 8 + c);
        }
        CP_COMMIT();
    };

    auto compute = [&](int s) {
        uint32_t a_base = sb + s * STAGE_BYTES;
        uint32_t b_base = a_base + OFF_B;
#pragma unroll
        for (int ks = 0; ks < 2; ks++) {
            const int kk = ks * 16 + 2 * q4;
            uint32_t ah[2][4];
#pragma unroll
            for (int mt = 0; mt < 2; mt++) {
                int r0 = wm * 32 + mt * 16 + g;
#pragma unroll
                for (int p = 0; p < 4; p++) {
                    int rr = r0 + (p & 1) * 8;
                    int kc = kk + (p >> 1) * 8;
                    float vx, vy;
                    asm volatile("ld.shared.v2.f32 {%0,%1}, [%2];"
                                 : "=f"(vx), "=f"(vy)
                                 : "r"(a_base + rr * SA_BYTES + kc * 4));
                    __half2 h = __floats2half2_rn(vx, vy);
                    ah[mt][p] = *(uint32_t*)&h;
                }
            }
#pragma unroll
            for (int j = 0; j < 8; j++) {
                int n = wn * 64 + j * 8 + g;
                uint32_t addr = b_base + n * SB_BYTES + ks * 64 + q4 * 8;
                uint32_t b0h, b0r, b1h, b1r;
                asm volatile("ld.shared.v2.b32 {%0,%1}, [%2];"
                             : "=r"(b0h), "=r"(b0r) : "r"(addr));
                asm volatile("ld.shared.v2.b32 {%0,%1}, [%2];"
                             : "=r"(b1h), "=r"(b1r) : "r"(addr + 32));
#pragma unroll
                for (int mt = 0; mt < 2; mt++) {
                    MMA_F16(acc[mt][j], ah[mt], b0h, b1h);   // Ah*Bh
                    MMA_F16(acc[mt][j], ah[mt], b0r, b1r);   // Ah*Br
                }
            }
        }
    };

    load_stage(0, 0);
    load_stage(1, 1);
    for (int t = 0; t < NKT; t++) {
        CP_WAIT1();
        __syncthreads();
        compute(t & 1);
        __syncthreads();
        if (t + 2 < NKT) load_stage(t & 1, t + 2);
        else             CP_COMMIT();                    // empty group keeps wait math valid
    }

    // ---- epilogue: gather + bias + relu + dot(W2) + reduce ----
    const int is64 = g_tk_is64;
    {   // stage gather matrix G[128][128] f32 into (reused) SMEM
        int row = tid >> 1, half = tid & 1;
        int m = m0 + row;
        int tok = tkw[is64 ? 2 * m : m];
        const float4* src = (const float4*)(W1 + (size_t)tok * HS1) + half * 16;
        float4* dst = (float4*)((float*)smem + row * SG + half * 64);
#pragma unroll
        for (int i = 0; i < 16; i++) dst[i] = src[i];
    }
    float b1v[16], w2v[16];
#pragma unroll
    for (int j = 0; j < 8; j++) {
        int col = wn * 64 + j * 8 + 2 * q4;
        b1v[j * 2] = b1[col];  b1v[j * 2 + 1] = b1[col + 1];
        w2v[j * 2] = W2[col];  w2v[j * 2 + 1] = W2[col + 1];
    }
    __syncthreads();

    float* red = (float*)(smem + OFF_RED);
    const float* G = (const float*)smem;
#pragma unroll
    for (int mt = 0; mt < 2; mt++)
#pragma unroll
        for (int h = 0; h < 2; h++) {
            int row = wm * 32 + mt * 16 + h * 8 + g;
            const float* Gr = G + row * SG + wn * 64;
            float p = 0.f;
#pragma unroll
            for (int j = 0; j < 8; j++) {
                float x0 = acc[mt][j][h * 2 + 0] + Gr[j * 8 + 2 * q4]     + b1v[j * 2];
                float x1 = acc[mt][j][h * 2 + 1] + Gr[j * 8 + 2 * q4 + 1] + b1v[j * 2 + 1];
                p = fmaf(fmaxf(x0, 0.f), w2v[j * 2],     p);
                p = fmaf(fmaxf(x1, 0.f), w2v[j * 2 + 1], p);
            }
            red[row * 9 + wn * 4 + q4] = p;
        }
    __syncthreads();

    if (tid < MT) {
        float s = 0.f;
#pragma unroll
        for (int x = 0; x < 8; x++) s += red[tid * 9 + x];
        out[m0 + tid] = s + b2[0];
    }
}

extern "C" void kernel_launch(void* const* d_in, const int* in_sizes, int n_in,
                              void* d_out, int out_size)
{
    const int*   tkw = (const int*)d_in[0];
    const float* hs0 = (const float*)d_in[1];
    const float* W1  = (const float*)d_in[2];
    const float* b1  = (const float*)d_in[3];
    const float* W2  = (const float*)d_in[4];
    const float* b2  = (const float*)d_in[5];
    float* out = (float*)d_out;

    const int M = in_sizes[1] / HID;   // tokens from hs0 (tk-dtype agnostic)

    cudaFuncSetAttribute(cls_mma_kernel,
                         cudaFuncAttributeMaxDynamicSharedMemorySize, SMEM_BYTES);

    prep_w_kernel<<<NKT, 256>>>(W1, (const unsigned int*)tkw);
    cls_mma_kernel<<<M / MT, 256, SMEM_BYTES>>>(tkw, hs0, W1, b1, W2, b2, out);
}

// round 11
// speedup vs baseline: 5.1384x; 1.0600x over previous
#include <cuda_runtime.h>
#include <cuda_fp16.h>
#include <cstdint>

#define VOCAB 32000
#define HID   768
#define HS1   128
#define MT    128
#define KT    32
#define NKT   (HID / KT)          // 24 K-tiles

#define SA    80                  // A row stride: 32 fp16 (64B) + 16B pad  -> ldmatrix conflict-free
#define SB    144                 // B row stride: 128B packed (h|r) + 16B pad
#define OFF_B 10240               // 128*SA
#define STAGE_BYTES 28672         // OFF_B + 128*SB
#define SMEM_BYTES  73728         // epilogue G(128*132*4) + red dominates
#define SG       132              // epilogue gather row stride (f32)
#define OFF_RED  67584            // 128*132*4

__device__ int g_tk_is64;
// packed fp16 weights per (tile t, n): 128B = [64B h: k0..31][64B r: k0..31]
__device__ uint4 g_Bpk[(size_t)NKT * HS1 * 8];

__device__ __forceinline__ uint32_t smem_u32(const void* p) {
    uint32_t a;
    asm("{ .reg .u64 t; cvta.to.shared.u64 t, %1; cvt.u32.u64 %0, t; }" : "=r"(a) : "l"(p));
    return a;
}
__device__ __forceinline__ void cp16(uint32_t dst, const void* src) {
    asm volatile("cp.async.ca.shared.global [%0], [%1], 16;" :: "r"(dst), "l"(src));
}
#define CP_COMMIT() asm volatile("cp.async.commit_group;" ::: "memory")
#define CP_WAIT1()  asm volatile("cp.async.wait_group 1;" ::: "memory")

#define LM4(r, addr)                                                            \
    asm volatile("ldmatrix.sync.aligned.m8n8.x4.shared.b16 {%0,%1,%2,%3}, [%4];"\
        : "=r"((r)[0]), "=r"((r)[1]), "=r"((r)[2]), "=r"((r)[3]) : "r"(addr))

#define MMA_F16(d, a, b0, b1)                                                   \
    asm volatile("mma.sync.aligned.m16n8k16.row.col.f32.f16.f16.f32 "           \
        "{%0,%1,%2,%3}, {%4,%5,%6,%7}, {%8,%9}, {%0,%1,%2,%3};"                 \
        : "+f"((d)[0]), "+f"((d)[1]), "+f"((d)[2]), "+f"((d)[3])                \
        : "r"((a)[0]), "r"((a)[1]), "r"((a)[2]), "r"((a)[3]), "r"(b0), "r"(b1))

// ---- prep: coalesced transpose + fp16 (value, residual) split; probe folded in ----
__global__ void prep_w_kernel(const float* __restrict__ W1,
                              const unsigned int* __restrict__ tkw) {
    __shared__ float sm[KT][HS1 + 4];
    const int t = blockIdx.x, tid = threadIdx.x;
    if (t == 0 && tid < 32) {   // tk dtype probe: int64 -> all odd words zero
        unsigned int v = (tid >= 1) ? tkw[2 * tid - 1] : 0u;
        unsigned int any = __ballot_sync(0xffffffffu, v != 0u);
        if (tid == 0) g_tk_is64 = (any == 0u) ? 1 : 0;
    }
#pragma unroll
    for (int i = 0; i < 16; i++) {            // coalesced read 32k x 128n
        int u = i * 256 + tid;
        int k = u >> 7, n = u & 127;
        sm[k][n] = W1[(size_t)(VOCAB + t * KT + k) * HS1 + n];
    }
    __syncthreads();
#pragma unroll
    for (int i = 0; i < 4; i++) {             // emit [n][h(64B)|r(64B)] k-order
        int u = i * 256 + tid;
        int n = u >> 3, c = u & 7;
        int part = c >> 2, k0 = (c & 3) * 8;
        uint4 o;
#pragma unroll
        for (int q = 0; q < 4; q++) {
            float x0 = sm[k0 + 2 * q][n], x1 = sm[k0 + 2 * q + 1][n];
            __half2 h = __floats2half2_rn(x0, x1);
            uint32_t w;
            if (part == 0) w = *(uint32_t*)&h;
            else {
                __half2 r = __floats2half2_rn(x0 - __low2float(h),
                                              x1 - __high2float(h));
                w = *(uint32_t*)&r;
            }
            ((uint32_t*)&o)[q] = w;
        }
        g_Bpk[((size_t)t * HS1 + n) * 8 + c] = o;
    }
}

// ---------------- main fused kernel ----------------
__global__ __launch_bounds__(256, 2)
void cls_mma_kernel(const int*   __restrict__ tkw,
                    const float* __restrict__ hs0,
                    const float* __restrict__ W1,
                    const float* __restrict__ b1,
                    const float* __restrict__ W2,
                    const float* __restrict__ b2,
                    float*       __restrict__ out)
{
    extern __shared__ char smem[];
    const uint32_t sb = smem_u32(smem);
    const int tid = threadIdx.x;
    const int lane = tid & 31, wid = tid >> 5;
    const int wm = wid & 3;            // warp row (4) -> 32 M-rows
    const int wn = wid >> 2;           // warp col (2) -> 64 N-cols
    const int g  = lane >> 2;          // 0..7
    const int q4 = lane & 3;           // 0..3
    const int m0 = blockIdx.x * MT;

    // ldmatrix per-thread source addresses
    const int aRow = (lane & 7) + ((lane >> 3) & 1) * 8;     // row within m16
    const int aK   = (lane >> 4) * 8;                        // k-half select
    const uint32_t aBase = (uint32_t)((wm * 32 + aRow) * SA + aK * 2);
    const uint32_t bBase = (uint32_t)(OFF_B + (wn * 64 + (lane & 7)) * SB
                                      + ((lane >> 3) & 1) * 16 + (lane >> 4) * 64);

    float acc[2][8][4];
#pragma unroll
    for (int mt = 0; mt < 2; mt++)
#pragma unroll
        for (int j = 0; j < 8; j++)
#pragma unroll
            for (int e = 0; e < 4; e++) acc[mt][j][e] = 0.f;

    const int r_ld = tid >> 3, c_ld = tid & 7;
    float4 aF[4];                                             // A(t) staging regs
    auto ldgA = [&](int t) {
#pragma unroll
        for (int i = 0; i < 4; i++)
            aF[i] = *(const float4*)(hs0 + (size_t)(m0 + r_ld + i * 32) * HID
                                     + t * KT + c_ld * 4);
    };
    auto stsA = [&](int s) {                                  // cvt f32->fp16 + STS.64
        uint32_t base = sb + s * STAGE_BYTES;
#pragma unroll
        for (int i = 0; i < 4; i++) {
            __half2 h0 = __floats2half2_rn(aF[i].x, aF[i].y);
            __half2 h1 = __floats2half2_rn(aF[i].z, aF[i].w);
            asm volatile("st.shared.v2.b32 [%0], {%1,%2};"
                :: "r"(base + (r_ld + i * 32) * SA + c_ld * 8),
                   "r"(*(uint32_t*)&h0), "r"(*(uint32_t*)&h1));
        }
    };
    auto cpB = [&](int s, int t) {
        uint32_t base = sb + s * STAGE_BYTES + OFF_B;
        const uint4* src = g_Bpk + (size_t)t * HS1 * 8;
#pragma unroll
        for (int i = 0; i < 4; i++) {
            int q = i * 256 + tid, n = q >> 3, c = q & 7;
            cp16(base + n * SB + c * 16, src + n * 8 + c);
        }
        CP_COMMIT();
    };

    auto compute = [&](int s) {
        uint32_t base = sb + s * STAGE_BYTES;
#pragma unroll
        for (int ks = 0; ks < 2; ks++) {
            uint32_t a0[4], a1[4];
            LM4(a0, base + aBase + ks * 32);                  // mt=0 m16k16 frag
            LM4(a1, base + aBase + 16 * SA + ks * 32);        // mt=1
#pragma unroll
            for (int j = 0; j < 8; j++) {
                uint32_t b[4];                                // {b0h,b1h,b0r,b1r}
                LM4(b, base + bBase + j * 8 * SB + ks * 32);
                MMA_F16(acc[0][j], a0, b[0], b[1]);
                MMA_F16(acc[1][j], a1, b[0], b[1]);
                MMA_F16(acc[0][j], a0, b[2], b[3]);
                MMA_F16(acc[1][j], a1, b[2], b[3]);
            }
        }
    };

    // ---- pipelined mainloop ----
    cpB(0, 0); cpB(1, 1);
    ldgA(0); stsA(0); ldgA(1);
    for (int t = 0; t < NKT; t++) {
        CP_WAIT1();                       // B(t) arrived
        __syncthreads();                  // A(t)/B(t) visible
        if (t + 1 < NKT) { stsA((t + 1) & 1); if (t + 2 < NKT) ldgA(t + 2); }
        compute(t & 1);
        __syncthreads();                  // stage t&1 free
        if (t + 2 < NKT) cpB(t & 1, t + 2); else CP_COMMIT();
    }

    // ---- epilogue: gather + bias + relu + dot(W2) + reduce ----
    const int is64 = g_tk_is64;
    {   // stage gather matrix G[128][128] f32 into (reused) SMEM
        int row = tid >> 1, half = tid & 1;
        int m = m0 + row;
        int tok = tkw[is64 ? 2 * m : m];
        const float4* src = (const float4*)(W1 + (size_t)tok * HS1) + half * 16;
        float4* dst = (float4*)((float*)smem + row * SG + half * 64);
#pragma unroll
        for (int i = 0; i < 16; i++) dst[i] = src[i];
    }
    float b1v[16], w2v[16];
#pragma unroll
    for (int j = 0; j < 8; j++) {
        int col = wn * 64 + j * 8 + 2 * q4;
        b1v[j * 2] = b1[col];  b1v[j * 2 + 1] = b1[col + 1];
        w2v[j * 2] = W2[col];  w2v[j * 2 + 1] = W2[col + 1];
    }
    __syncthreads();

    float* red = (float*)(smem + OFF_RED);
    const float* G = (const float*)smem;
#pragma unroll
    for (int mt = 0; mt < 2; mt++)
#pragma unroll
        for (int h = 0; h < 2; h++) {
            int row = wm * 32 + mt * 16 + h * 8 + g;
            const float* Gr = G + row * SG + wn * 64;
            float p = 0.f;
#pragma unroll
            for (int j = 0; j < 8; j++) {
                float x0 = acc[mt][j][h * 2 + 0] + Gr[j * 8 + 2 * q4]     + b1v[j * 2];
                float x1 = acc[mt][j][h * 2 + 1] + Gr[j * 8 + 2 * q4 + 1] + b1v[j * 2 + 1];
                p = fmaf(fmaxf(x0, 0.f), w2v[j * 2],     p);
                p = fmaf(fmaxf(x1, 0.f), w2v[j * 2 + 1], p);
            }
            red[row * 9 + wn * 4 + q4] = p;
        }
    __syncthreads();

    if (tid < MT) {
        float s = 0.f;
#pragma unroll
        for (int x = 0; x < 8; x++) s += red[tid * 9 + x];
        out[m0 + tid] = s + b2[0];
    }
}

extern "C" void kernel_launch(void* const* d_in, const int* in_sizes, int n_in,
                              void* d_out, int out_size)
{
    const int*   tkw = (const int*)d_in[0];
    const float* hs0 = (const float*)d_in[1];
    const float* W1  = (const float*)d_in[2];
    const float* b1  = (const float*)d_in[3];
    const float* W2  = (const float*)d_in[4];
    const float* b2  = (const float*)d_in[5];
    float* out = (float*)d_out;

    const int M = in_sizes[1] / HID;   // tokens from hs0 (tk-dtype agnostic)

    cudaFuncSetAttribute(cls_mma_kernel,
                         cudaFuncAttributeMaxDynamicSharedMemorySize, SMEM_BYTES);

    prep_w_kernel<<<NKT, 256>>>(W1, (const unsigned int*)tkw);
    cls_mma_kernel<<<M / MT, 256, SMEM_BYTES>>>(tkw, hs0, W1, b1, W2, b2, out);
}

// round 12
// speedup vs baseline: 7.2962x; 1.4200x over previous
#include <cuda_runtime.h>
#include <cuda_fp16.h>
#include <cstdint>

#define VOCAB 32000
#define HID   768
#define HS1   128
#define MT    128
#define KT    32
#define NKT   (HID / KT)          // 24 K-tiles

#define SA    80                  // A row stride: 32 fp16 (64B) + 16B pad
#define SB    80                  // B row stride: 64B h-only + 16B pad
#define OFF_B 10240               // 128*SA
#define STAGE_BYTES 20480         // OFF_B + 128*SB
#define SMEM_BYTES  73728         // epilogue G + red dominates
#define SG       132              // epilogue gather row stride (f32)
#define OFF_RED  67584            // 128*132*4

__device__ int g_tk_is64;
// packed fp16 weights per (tile t, n): 64B = k0..31 as half2 pairs (h only)
__device__ uint4 g_Bpk[(size_t)NKT * HS1 * 4];

__device__ __forceinline__ uint32_t smem_u32(const void* p) {
    uint32_t a;
    asm("{ .reg .u64 t; cvta.to.shared.u64 t, %1; cvt.u32.u64 %0, t; }" : "=r"(a) : "l"(p));
    return a;
}
__device__ __forceinline__ void cp16(uint32_t dst, const void* src) {
    asm volatile("cp.async.ca.shared.global [%0], [%1], 16;" :: "r"(dst), "l"(src));
}
#define CP_COMMIT() asm volatile("cp.async.commit_group;" ::: "memory")
#define CP_WAIT1()  asm volatile("cp.async.wait_group 1;" ::: "memory")

#define LM4(r, addr)                                                            \
    asm volatile("ldmatrix.sync.aligned.m8n8.x4.shared.b16 {%0,%1,%2,%3}, [%4];"\
        : "=r"((r)[0]), "=r"((r)[1]), "=r"((r)[2]), "=r"((r)[3]) : "r"(addr))

#define MMA_F16(d, a, b0, b1)                                                   \
    asm volatile("mma.sync.aligned.m16n8k16.row.col.f32.f16.f16.f32 "           \
        "{%0,%1,%2,%3}, {%4,%5,%6,%7}, {%8,%9}, {%0,%1,%2,%3};"                 \
        : "+f"((d)[0]), "+f"((d)[1]), "+f"((d)[2]), "+f"((d)[3])                \
        : "r"((a)[0]), "r"((a)[1]), "r"((a)[2]), "r"((a)[3]), "r"(b0), "r"(b1))

// ---- prep: coalesced transpose + fp16 convert; tk-dtype probe folded in ----
__global__ void prep_w_kernel(const float* __restrict__ W1,
                              const unsigned int* __restrict__ tkw) {
    __shared__ float sm[KT][HS1 + 4];
    const int t = blockIdx.x, tid = threadIdx.x;
    if (t == 0 && tid < 32) {   // tk dtype probe: int64 -> all odd words zero
        unsigned int v = (tid >= 1) ? tkw[2 * tid - 1] : 0u;
        unsigned int any = __ballot_sync(0xffffffffu, v != 0u);
        if (tid == 0) g_tk_is64 = (any == 0u) ? 1 : 0;
    }
#pragma unroll
    for (int i = 0; i < 16; i++) {            // coalesced read 32k x 128n
        int u = i * 256 + tid;
        int k = u >> 7, n = u & 127;
        sm[k][n] = W1[(size_t)(VOCAB + t * KT + k) * HS1 + n];
    }
    __syncthreads();
#pragma unroll
    for (int i = 0; i < 2; i++) {             // emit [n][64B: k-major half2]
        int u = i * 256 + tid;
        int n = u >> 2, c = u & 3;
        int k0 = c * 8;
        uint4 o;
#pragma unroll
        for (int q = 0; q < 4; q++) {
            __half2 h = __floats2half2_rn(sm[k0 + 2 * q][n], sm[k0 + 2 * q + 1][n]);
            ((uint32_t*)&o)[q] = *(uint32_t*)&h;
        }
        g_Bpk[((size_t)t * HS1 + n) * 4 + c] = o;
    }
}

// ---------------- main fused kernel ----------------
__global__ __launch_bounds__(256, 2)
void cls_mma_kernel(const int*   __restrict__ tkw,
                    const float* __restrict__ hs0,
                    const float* __restrict__ W1,
                    const float* __restrict__ b1,
                    const float* __restrict__ W2,
                    const float* __restrict__ b2,
                    float*       __restrict__ out)
{
    extern __shared__ char smem[];
    const uint32_t sb = smem_u32(smem);
    const int tid = threadIdx.x;
    const int lane = tid & 31, wid = tid >> 5;
    const int wm = wid & 3;            // warp row (4) -> 32 M-rows
    const int wn = wid >> 2;           // warp col (2) -> 64 N-cols
    const int g  = lane >> 2;          // 0..7
    const int q4 = lane & 3;           // 0..3
    const int m0 = blockIdx.x * MT;

    // ldmatrix per-thread source addresses
    const int aRow = (lane & 7) + ((lane >> 3) & 1) * 8;
    const int aK   = (lane >> 4) * 8;
    const uint32_t aBase = (uint32_t)((wm * 32 + aRow) * SA + aK * 2);
    // B: matrices {b0(j0), b1(j0), b0(j1), b1(j1)}; lanes16-31 -> j1 (+8 n rows)
    const uint32_t bBase = (uint32_t)(OFF_B
        + (wn * 64 + (lane & 7) + ((lane >> 4) & 1) * 8) * SB
        + ((lane >> 3) & 1) * 16);

    float acc[2][8][4];
#pragma unroll
    for (int mt = 0; mt < 2; mt++)
#pragma unroll
        for (int j = 0; j < 8; j++)
#pragma unroll
            for (int e = 0; e < 4; e++) acc[mt][j][e] = 0.f;

    const int r_ld = tid >> 3, c_ld = tid & 7;
    float4 aF[4];                                             // A(t) staging regs
    auto ldgA = [&](int t) {
#pragma unroll
        for (int i = 0; i < 4; i++)
            aF[i] = *(const float4*)(hs0 + (size_t)(m0 + r_ld + i * 32) * HID
                                     + t * KT + c_ld * 4);
    };
    auto stsA = [&](int s) {                                  // cvt f32->fp16 + STS.64
        uint32_t base = sb + s * STAGE_BYTES;
#pragma unroll
        for (int i = 0; i < 4; i++) {
            __half2 h0 = __floats2half2_rn(aF[i].x, aF[i].y);
            __half2 h1 = __floats2half2_rn(aF[i].z, aF[i].w);
            asm volatile("st.shared.v2.b32 [%0], {%1,%2};"
                :: "r"(base + (r_ld + i * 32) * SA + c_ld * 8),
                   "r"(*(uint32_t*)&h0), "r"(*(uint32_t*)&h1));
        }
    };
    auto cpB = [&](int s, int t) {
        uint32_t base = sb + s * STAGE_BYTES + OFF_B;
        const uint4* src = g_Bpk + (size_t)t * HS1 * 4;
#pragma unroll
        for (int i = 0; i < 2; i++) {
            int q = i * 256 + tid, n = q >> 2, c = q & 3;
            cp16(base + n * SB + c * 16, src + n * 4 + c);
        }
        CP_COMMIT();
    };

    auto compute = [&](int s) {
        uint32_t base = sb + s * STAGE_BYTES;
#pragma unroll
        for (int ks = 0; ks < 2; ks++) {
            uint32_t a0[4], a1[4];
            LM4(a0, base + aBase + ks * 32);                  // mt=0 m16k16 frag
            LM4(a1, base + aBase + 16 * SA + ks * 32);        // mt=1
#pragma unroll
            for (int p = 0; p < 4; p++) {                     // j-pairs
                uint32_t b[4];                                // {b0,b1}(j0) {b0,b1}(j1)
                LM4(b, base + bBase + p * 16 * SB + ks * 32);
                MMA_F16(acc[0][2 * p],     a0, b[0], b[1]);
                MMA_F16(acc[1][2 * p],     a1, b[0], b[1]);
                MMA_F16(acc[0][2 * p + 1], a0, b[2], b[3]);
                MMA_F16(acc[1][2 * p + 1], a1, b[2], b[3]);
            }
        }
    };

    // ---- pipelined mainloop ----
    cpB(0, 0); cpB(1, 1);
    ldgA(0); stsA(0); ldgA(1);
    for (int t = 0; t < NKT; t++) {
        CP_WAIT1();                       // B(t) arrived
        __syncthreads();                  // A(t)/B(t) visible
        if (t + 1 < NKT) { stsA((t + 1) & 1); if (t + 2 < NKT) ldgA(t + 2); }
        compute(t & 1);
        __syncthreads();                  // stage t&1 free
        if (t + 2 < NKT) cpB(t & 1, t + 2); else CP_COMMIT();
    }

    // ---- epilogue: gather + bias + relu + dot(W2) + reduce ----
    const int is64 = g_tk_is64;
    {   // stage gather matrix G[128][128] f32 into (reused) SMEM
        int row = tid >> 1, half = tid & 1;
        int m = m0 + row;
        int tok = tkw[is64 ? 2 * m : m];
        const float4* src = (const float4*)(W1 + (size_t)tok * HS1) + half * 16;
        float4* dst = (float4*)((float*)smem + row * SG + half * 64);
#pragma unroll
        for (int i = 0; i < 16; i++) dst[i] = src[i];
    }
    float b1v[16], w2v[16];
#pragma unroll
    for (int j = 0; j < 8; j++) {
        int col = wn * 64 + j * 8 + 2 * q4;
        b1v[j * 2] = b1[col];  b1v[j * 2 + 1] = b1[col + 1];
        w2v[j * 2] = W2[col];  w2v[j * 2 + 1] = W2[col + 1];
    }
    __syncthreads();

    float* red = (float*)(smem + OFF_RED);
    const float* G = (const float*)smem;
#pragma unroll
    for (int mt = 0; mt < 2; mt++)
#pragma unroll
        for (int h = 0; h < 2; h++) {
            int row = wm * 32 + mt * 16 + h * 8 + g;
            const float* Gr = G + row * SG + wn * 64;
            float p = 0.f;
#pragma unroll
            for (int j = 0; j < 8; j++) {
                float x0 = acc[mt][j][h * 2 + 0] + Gr[j * 8 + 2 * q4]     + b1v[j * 2];
                float x1 = acc[mt][j][h * 2 + 1] + Gr[j * 8 + 2 * q4 + 1] + b1v[j * 2 + 1];
                p = fmaf(fmaxf(x0, 0.f), w2v[j * 2],     p);
                p = fmaf(fmaxf(x1, 0.f), w2v[j * 2 + 1], p);
            }
            red[row * 9 + wn * 4 + q4] = p;
        }
    __syncthreads();

    if (tid < MT) {
        float s = 0.f;
#pragma unroll
        for (int x = 0; x < 8; x++) s += red[tid * 9 + x];
        out[m0 + tid] = s + b2[0];
    }
}

extern "C" void kernel_launch(void* const* d_in, const int* in_sizes, int n_in,
                              void* d_out, int out_size)
{
    const int*   tkw = (const int*)d_in[0];
    const float* hs0 = (const float*)d_in[1];
    const float* W1  = (const float*)d_in[2];
    const float* b1  = (const float*)d_in[3];
    const float* W2  = (const float*)d_in[4];
    const float* b2  = (const float*)d_in[5];
    float* out = (float*)d_out;

    const int M = in_sizes[1] / HID;   // tokens from hs0 (tk-dtype agnostic)

    cudaFuncSetAttribute(cls_mma_kernel,
                         cudaFuncAttributeMaxDynamicSharedMemorySize, SMEM_BYTES);

    prep_w_kernel<<<NKT, 256>>>(W1, (const unsigned int*)tkw);
    cls_mma_kernel<<<M / MT, 256, SMEM_BYTES>>>(tkw, hs0, W1, b1, W2, b2, out);
}